// round 12
// baseline (speedup 1.0000x reference)
#include <cuda_runtime.h>
#include <cstdint>

// LSTMPredictor: B=256, T=1024, H=128, 2-layer LSTM + linear head.
// 32 clusters x 4 CTAs x 256 threads. Layer-pipelined (R10): iteration i
// computes h1(i) and h2(i-1); ONE cluster barrier per iteration.
// R11: sync-free iteration body. Rows are unit-major per warp (warp w owns
// units w*4..w*4+3, gates 0..3), so the mma.sync output tile is transposed
// IN-WARP (2x shfl_xor rounds) to hand each thread all 4 gates of one
// (unit,batch). No gate staging smem, no __syncthreads; biases/wx/wout in
// registers; x via per-thread prefetched LDG. Output overlaps next MMA.

namespace {

constexpr int Bt = 256;
constexpr int Tt = 1024;
constexpr int Ht = 128;
constexpr int CL = 4;
constexpr int BC = 8;
constexpr int NTH = 256;

// smem (floats): only the h exchange tiles
constexpr int OFF_HT1 = 0;      // h1 transposed [k][b]: 2 slot x 128 x 8
constexpr int OFF_HT2 = 2048;   // h2
constexpr int SM_FLOATS = 4096;
constexpr int SM_BYTES = SM_FLOATS * 4;  // 16 KB

__device__ __forceinline__ uint32_t s2u(const void* p) {
    return (uint32_t)__cvta_generic_to_shared(p);
}
__device__ __forceinline__ float to_tf32(float x) {
    float r;
    asm("cvt.rna.tf32.f32 %0, %1;" : "=f"(r) : "f"(x));
    return r;
}
__device__ __forceinline__ uint32_t tfbits(float x) {
    return __float_as_uint(to_tf32(x));
}
__device__ __forceinline__ void mma8(float* d, const uint32_t* a, uint32_t b0,
                                     uint32_t b1) {
    asm volatile(
        "mma.sync.aligned.m16n8k8.row.col.f32.tf32.tf32.f32 "
        "{%0,%1,%2,%3}, {%4,%5,%6,%7}, {%8,%9}, {%0,%1,%2,%3};"
        : "+f"(d[0]), "+f"(d[1]), "+f"(d[2]), "+f"(d[3])
        : "r"(a[0]), "r"(a[1]), "r"(a[2]), "r"(a[3]), "r"(b0), "r"(b1));
}
__device__ __forceinline__ void st_remote(uint32_t laddr, uint32_t peer, float v) {
    uint32_t r;
    asm("mapa.shared::cluster.u32 %0, %1, %2;" : "=r"(r) : "r"(laddr), "r"(peer));
    asm volatile("st.shared::cluster.f32 [%0], %1;" ::"r"(r), "f"(v) : "memory");
}
__device__ __forceinline__ void cl_arrive() {
    asm volatile("barrier.cluster.arrive.aligned;" ::: "memory");
}
__device__ __forceinline__ void cl_wait() {
    asm volatile("barrier.cluster.wait.aligned;" ::: "memory");
}
__device__ __forceinline__ float sigf(float x) {
    return 1.0f / (1.0f + __expf(-x));
}
__device__ __forceinline__ float tanh_fast(float x) {
    return 2.0f / (1.0f + __expf(-2.0f * x)) - 1.0f;
}

// In-warp transpose of an m16n8 accumulator tile (rows unit-major):
// input e0..e3 = (row g8, col 2q), (g8, 2q+1), (g8+8, 2q), (g8+8, 2q+1);
// output f[0..3] = gates 0..3 of (unit 2*bit2+bit4, batch 2*q+bit3).
__device__ __forceinline__ void xpose(float e0, float e1, float e2, float e3,
                                      int lane, float* f) {
    const bool beta = (lane >> 2) & 1;
    float o0 = beta ? e0 : e2, o1 = beta ? e1 : e3;
    o0 = __shfl_xor_sync(0xffffffffu, o0, 4);
    o1 = __shfl_xor_sync(0xffffffffu, o1, 4);
    const float k0 = beta ? e2 : e0, k1 = beta ? e3 : e1;
    const float n0 = beta ? o0 : k0, n1 = beta ? o1 : k1;
    const float n2 = beta ? k0 : o0, n3 = beta ? k1 : o1;
    const bool gam = (lane >> 3) & 1;
    float q0 = gam ? n0 : n1, q1 = gam ? n2 : n3;
    q0 = __shfl_xor_sync(0xffffffffu, q0, 8);
    q1 = __shfl_xor_sync(0xffffffffu, q1, 8);
    const float m0 = gam ? n1 : n0, m1 = gam ? n3 : n2;
    f[0] = gam ? q0 : m0;
    f[1] = gam ? q1 : m1;
    f[2] = gam ? m0 : q0;
    f[3] = gam ? m1 : q1;
}

__global__ void __launch_bounds__(NTH, 1) lstm_mma_kernel(
    const float* __restrict__ x, const float* __restrict__ Wih1,
    const float* __restrict__ Whh1, const float* __restrict__ bih1,
    const float* __restrict__ bhh1, const float* __restrict__ Wih2,
    const float* __restrict__ Whh2, const float* __restrict__ bih2,
    const float* __restrict__ bhh2, const float* __restrict__ Wout,
    const float* __restrict__ bout, float* __restrict__ out) {
    extern __shared__ float sm[];
    float* hT1 = sm + OFF_HT1;
    float* hT2 = sm + OFF_HT2;

    const int tid = threadIdx.x;
    const int lane = tid & 31;
    const int warp = tid >> 5;
    const int rank = blockIdx.x & 3;
    const int bbase = (blockIdx.x >> 2) * BC;
    const int U0 = rank * 32;

    // ---- MMA fragment coordinates (rows unit-major within warp) ----
    const int q = lane & 3;
    const int g8 = lane >> 2;  // 0..7: gate = g8&3, unit_in_warp = g8>>2 (+2 for row+8)
    const int qg = q * 8 + g8;  // B-frag word offset (conflict-free)
    // A-frag global weight rows: G0 = gate*128 + U0 + w*4 + (g8>>2); G1 = G0+2
    const int G0 = (g8 & 3) * 128 + U0 + warp * 4 + (g8 >> 2);
    const int G1 = G0 + 2;

    // ---- weights -> registers as tf32 A-fragments ----
    uint32_t w1[64], w2h[64], w2i[64];
#pragma unroll
    for (int kt = 0; kt < 16; ++kt) {
        const int k0 = kt * 8 + q;
        w1[kt * 4 + 0] = tfbits(Whh1[G0 * Ht + k0]);
        w1[kt * 4 + 1] = tfbits(Whh1[G1 * Ht + k0]);
        w1[kt * 4 + 2] = tfbits(Whh1[G0 * Ht + k0 + 4]);
        w1[kt * 4 + 3] = tfbits(Whh1[G1 * Ht + k0 + 4]);
        w2h[kt * 4 + 0] = tfbits(Whh2[G0 * Ht + k0]);
        w2h[kt * 4 + 1] = tfbits(Whh2[G1 * Ht + k0]);
        w2h[kt * 4 + 2] = tfbits(Whh2[G0 * Ht + k0 + 4]);
        w2h[kt * 4 + 3] = tfbits(Whh2[G1 * Ht + k0 + 4]);
        w2i[kt * 4 + 0] = tfbits(Wih2[G0 * Ht + k0]);
        w2i[kt * 4 + 1] = tfbits(Wih2[G1 * Ht + k0]);
        w2i[kt * 4 + 2] = tfbits(Wih2[G0 * Ht + k0 + 4]);
        w2i[kt * 4 + 3] = tfbits(Wih2[G1 * Ht + k0 + 4]);
    }

    // ---- epilogue identity (from transpose output layout) ----
    const int u_l = ((lane >> 2) & 1) * 2 + ((lane >> 4) & 1);  // 0..3
    const int gU = U0 + warp * 4 + u_l;                          // global unit
    const int bb = ((lane & 3) << 1) | ((lane >> 3) & 1);        // batch 0..7
    const int hword = gU * 8 + bb;

    // per-thread scalar params in registers
    float bsA[4], wxr[4], bsB[4];
#pragma unroll
    for (int g = 0; g < 4; ++g) {
        const int G = g * 128 + gU;
        bsA[g] = bih1[G] + bhh1[G];
        wxr[g] = Wih1[G];
        bsB[g] = bih2[G] + bhh2[G];
    }
    float wor[4];
#pragma unroll
    for (int j = 0; j < 4; ++j) wor[j] = Wout[lane + 32 * j];
    const float boutr = bout[0];

    // zero h tiles (both slots)
    for (int i = tid; i < 4096; i += NTH) sm[i] = 0.0f;
    __syncthreads();
    cl_arrive();
    cl_wait();  // peers' h buffers zeroed

    const uint32_t h1u = s2u(hT1);
    const uint32_t h2u = s2u(hT2);
    const uint32_t p1 = (rank + 1) & 3, p2r = (rank + 2) & 3, p3 = (rank + 3) & 3;

    float c1 = 0.0f, c2 = 0.0f;
    const int xb = (bbase + bb) * Tt;
    float xv_cur = x[xb];

    // iteration i: h1(i) -> hT1 slot i&1 ; h2(i-1) -> hT2 slot (i-1)&1
    for (int i = 0; i <= Tt; ++i) {
        const int p = i & 1;
        const int pp = p ^ 1;
        const bool doA = (i < Tt);
        const bool doB = (i > 0);

        float xv_nxt = 0.0f;
        if (doA && i + 1 < Tt) xv_nxt = x[xb + i + 1];  // prefetch

        // ===== MMA: D1 = Whh1@h1(i-1); D2 = Whh2@h2(i-2) + Wih2@h1(i-1) =====
        float d1a[4] = {0, 0, 0, 0}, d1b[4] = {0, 0, 0, 0};
        float d2a[4] = {0, 0, 0, 0}, d2b[4] = {0, 0, 0, 0};
        float d2c[4] = {0, 0, 0, 0}, d2d[4] = {0, 0, 0, 0};
        {
            const float* h1p = hT1 + pp * 1024;  // h1(i-1)
            const float* h2p = hT2 + p * 1024;   // h2(i-2)
            if (doA && doB) {
#pragma unroll
                for (int kt = 0; kt < 16; ++kt) {
                    const uint32_t b0 = __float_as_uint(h1p[kt * 64 + qg]);
                    const uint32_t b1 = __float_as_uint(h1p[kt * 64 + 32 + qg]);
                    const uint32_t e0 = __float_as_uint(h2p[kt * 64 + qg]);
                    const uint32_t e1 = __float_as_uint(h2p[kt * 64 + 32 + qg]);
                    mma8((kt & 1) ? d1b : d1a, &w1[kt * 4], b0, b1);
                    mma8((kt & 1) ? d2b : d2a, &w2h[kt * 4], e0, e1);
                    mma8((kt & 1) ? d2d : d2c, &w2i[kt * 4], b0, b1);
                }
            } else if (doA) {  // i == 0
#pragma unroll
                for (int kt = 0; kt < 16; ++kt) {
                    const uint32_t b0 = __float_as_uint(h1p[kt * 64 + qg]);
                    const uint32_t b1 = __float_as_uint(h1p[kt * 64 + 32 + qg]);
                    mma8((kt & 1) ? d1b : d1a, &w1[kt * 4], b0, b1);
                }
            } else {  // i == Tt
#pragma unroll
                for (int kt = 0; kt < 16; ++kt) {
                    const uint32_t b0 = __float_as_uint(h1p[kt * 64 + qg]);
                    const uint32_t b1 = __float_as_uint(h1p[kt * 64 + 32 + qg]);
                    const uint32_t e0 = __float_as_uint(h2p[kt * 64 + qg]);
                    const uint32_t e1 = __float_as_uint(h2p[kt * 64 + 32 + qg]);
                    mma8((kt & 1) ? d2b : d2a, &w2h[kt * 4], e0, e1);
                    mma8((kt & 1) ? d2d : d2c, &w2i[kt * 4], b0, b1);
                }
            }
        }

        // ===== epilogue A: in-warp transpose -> c1/h1(i) slot p, push =====
        if (doA) {
            float f[4];
            xpose(d1a[0] + d1b[0], d1a[1] + d1b[1], d1a[2] + d1b[2],
                  d1a[3] + d1b[3], lane, f);
            const float gi = f[0] + bsA[0] + xv_cur * wxr[0];
            const float gf = f[1] + bsA[1] + xv_cur * wxr[1];
            const float gg = f[2] + bsA[2] + xv_cur * wxr[2];
            const float go = f[3] + bsA[3] + xv_cur * wxr[3];
            c1 = sigf(gf) * c1 + sigf(gi) * tanh_fast(gg);
            const float h1v = to_tf32(sigf(go) * tanh_fast(c1));
            hT1[p * 1024 + hword] = h1v;
            const uint32_t la = h1u + (uint32_t)(p * 1024 + hword) * 4u;
            st_remote(la, p1, h1v);
            st_remote(la, p2r, h1v);
            st_remote(la, p3, h1v);
        }
        // ===== epilogue B: transpose -> c2/h2(i-1) slot pp, push =====
        if (doB) {
            float f[4];
            xpose(d2a[0] + d2b[0] + d2c[0] + d2d[0],
                  d2a[1] + d2b[1] + d2c[1] + d2d[1],
                  d2a[2] + d2b[2] + d2c[2] + d2d[2],
                  d2a[3] + d2b[3] + d2c[3] + d2d[3], lane, f);
            const float gi = f[0] + bsB[0];
            const float gf = f[1] + bsB[1];
            const float gg = f[2] + bsB[2];
            const float go = f[3] + bsB[3];
            c2 = sigf(gf) * c2 + sigf(gi) * tanh_fast(gg);
            const float h2v = to_tf32(sigf(go) * tanh_fast(c2));
            hT2[pp * 1024 + hword] = h2v;
            const uint32_t la = h2u + (uint32_t)(pp * 1024 + hword) * 4u;
            st_remote(la, p1, h2v);
            st_remote(la, p2r, h2v);
            st_remote(la, p3, h2v);
        }

        // ===== single cluster barrier: h1(i) + h2(i-1) published =====
        cl_arrive();
        cl_wait();

        // ===== output(i-1): warps 6,7 (overlaps next iteration's MMA) =====
        if (doB && warp >= 6) {
            const int bl = rank * 2 + (warp - 6);
            const float* h2c = hT2 + pp * 1024;
            float s = 0.0f;
#pragma unroll
            for (int j = 0; j < 4; ++j) {
                const int k = lane + 32 * j;
                s += h2c[k * 8 + bl] * wor[j];
            }
            s += __shfl_xor_sync(0xffffffffu, s, 16);
            s += __shfl_xor_sync(0xffffffffu, s, 8);
            s += __shfl_xor_sync(0xffffffffu, s, 4);
            s += __shfl_xor_sync(0xffffffffu, s, 2);
            s += __shfl_xor_sync(0xffffffffu, s, 1);
            if (lane == 0) out[(bbase + bl) * Tt + (i - 1)] = s + boutr;
        }
        xv_cur = xv_nxt;
    }

    // exit safety: no CTA leaves while peers could still target its smem
    cl_arrive();
    cl_wait();
}

}  // namespace

extern "C" void kernel_launch(void* const* d_in, const int* in_sizes, int n_in,
                              void* d_out, int out_size) {
    (void)in_sizes;
    (void)n_in;
    (void)out_size;
    const float* x = (const float*)d_in[0];
    const float* Wih1 = (const float*)d_in[1];
    const float* Whh1 = (const float*)d_in[2];
    const float* bih1 = (const float*)d_in[3];
    const float* bhh1 = (const float*)d_in[4];
    const float* Wih2 = (const float*)d_in[5];
    const float* Whh2 = (const float*)d_in[6];
    const float* bih2 = (const float*)d_in[7];
    const float* bhh2 = (const float*)d_in[8];
    const float* Wout = (const float*)d_in[9];
    const float* bout = (const float*)d_in[10];
    float* out = (float*)d_out;

    cudaFuncSetAttribute(lstm_mma_kernel,
                         cudaFuncAttributeMaxDynamicSharedMemorySize, SM_BYTES);

    cudaLaunchConfig_t cfg = {};
    cfg.gridDim = dim3((Bt / BC) * CL, 1, 1);  // 128 CTAs = 32 clusters of 4
    cfg.blockDim = dim3(NTH, 1, 1);
    cfg.dynamicSmemBytes = SM_BYTES;
    cfg.stream = 0;
    cudaLaunchAttribute attrs[1];
    attrs[0].id = cudaLaunchAttributeClusterDimension;
    attrs[0].val.clusterDim.x = CL;
    attrs[0].val.clusterDim.y = 1;
    attrs[0].val.clusterDim.z = 1;
    cfg.attrs = attrs;
    cfg.numAttrs = 1;

    cudaLaunchKernelEx(&cfg, lstm_mma_kernel, x, Wih1, Whh1, bih1, bhh1, Wih2,
                       Whh2, bih2, bhh2, Wout, bout, out);
}

// round 13
// speedup vs baseline: 1.1758x; 1.1758x over previous
#include <cuda_runtime.h>
#include <cstdint>

// LSTMPredictor: B=256, T=1024, H=128, 2-layer LSTM + linear head.
// 32 clusters x 4 CTAs x 256 threads. Layer-pipelined: iteration i computes
// h1(i) and h2(i-1); ONE cluster barrier per iteration (R10 structure).
// R12 changes vs R10:
//  - MMA block split in two phases: D1 -> sync -> epiA(+h1 push) -> D2 ->
//    sync -> epiB(+h2 push) -> arrive. h1's DSMEM drain hides behind D2 MMAs.
//  - __fdividef in sigmoid/tanh (MUFU.RCP instead of potential IEEE div).
//  - x prefetch + staging in the arrive->wait gap.

namespace {

constexpr int Bt = 256;
constexpr int Tt = 1024;
constexpr int Ht = 128;
constexpr int CL = 4;
constexpr int BC = 8;
constexpr int NTH = 256;

// smem (floats)
constexpr int OFF_HT1 = 0;      // h1 transposed [k][b]: 2 slot x 128 x 8
constexpr int OFF_HT2 = 2048;   // h2
constexpr int OFF_GA  = 4096;   // gates1 staging [128 r][8 b]
constexpr int OFF_GB  = 5120;   // gates2 staging
constexpr int OFF_BS1 = 6144;   // 128
constexpr int OFF_WX  = 6272;   // 128
constexpr int OFF_BS2 = 6400;   // 128
constexpr int OFF_WO  = 6528;   // 128
constexpr int OFF_X   = 6656;   // 2 slot x 8
constexpr int OFF_BO  = 6672;   // 1 (+pad)
constexpr int SM_FLOATS = 6676;
constexpr int SM_BYTES = SM_FLOATS * 4;  // ~26.7 KB

__device__ __forceinline__ uint32_t s2u(const void* p) {
    return (uint32_t)__cvta_generic_to_shared(p);
}
__device__ __forceinline__ float to_tf32(float x) {
    float r;
    asm("cvt.rna.tf32.f32 %0, %1;" : "=f"(r) : "f"(x));
    return r;
}
__device__ __forceinline__ uint32_t tfbits(float x) {
    return __float_as_uint(to_tf32(x));
}
__device__ __forceinline__ void mma8(float* d, const uint32_t* a, uint32_t b0,
                                     uint32_t b1) {
    asm volatile(
        "mma.sync.aligned.m16n8k8.row.col.f32.tf32.tf32.f32 "
        "{%0,%1,%2,%3}, {%4,%5,%6,%7}, {%8,%9}, {%0,%1,%2,%3};"
        : "+f"(d[0]), "+f"(d[1]), "+f"(d[2]), "+f"(d[3])
        : "r"(a[0]), "r"(a[1]), "r"(a[2]), "r"(a[3]), "r"(b0), "r"(b1));
}
__device__ __forceinline__ void st_remote(uint32_t laddr, uint32_t peer, float v) {
    uint32_t r;
    asm("mapa.shared::cluster.u32 %0, %1, %2;" : "=r"(r) : "r"(laddr), "r"(peer));
    asm volatile("st.shared::cluster.f32 [%0], %1;" ::"r"(r), "f"(v) : "memory");
}
__device__ __forceinline__ void cl_arrive() {
    asm volatile("barrier.cluster.arrive.aligned;" ::: "memory");
}
__device__ __forceinline__ void cl_wait() {
    asm volatile("barrier.cluster.wait.aligned;" ::: "memory");
}
// fast sigmoid/tanh: MUFU.EX2 + MUFU.RCP (no IEEE division)
__device__ __forceinline__ float sigf(float x) {
    return __fdividef(1.0f, 1.0f + __expf(-x));
}
__device__ __forceinline__ float tanh_fast(float x) {
    return __fdividef(2.0f, 1.0f + __expf(-2.0f * x)) - 1.0f;
}

__global__ void __launch_bounds__(NTH, 1) lstm_mma_kernel(
    const float* __restrict__ x, const float* __restrict__ Wih1,
    const float* __restrict__ Whh1, const float* __restrict__ bih1,
    const float* __restrict__ bhh1, const float* __restrict__ Wih2,
    const float* __restrict__ Whh2, const float* __restrict__ bih2,
    const float* __restrict__ bhh2, const float* __restrict__ Wout,
    const float* __restrict__ bout, float* __restrict__ out) {
    extern __shared__ float sm[];
    float* hT1 = sm + OFF_HT1;
    float* hT2 = sm + OFF_HT2;
    float* gbA = sm + OFF_GA;
    float* gbB = sm + OFF_GB;
    float* bs1s = sm + OFF_BS1;
    float* wxs = sm + OFF_WX;
    float* bs2s = sm + OFF_BS2;
    float* wos = sm + OFF_WO;
    float* xS = sm + OFF_X;
    float* boS = sm + OFF_BO;

    const int tid = threadIdx.x;
    const int lane = tid & 31;
    const int warp = tid >> 5;
    const int rank = blockIdx.x & 3;
    const int bbase = (blockIdx.x >> 2) * BC;
    const int U0 = rank * 32;

    // ---- per-thread MMA fragment coordinates ----
    const int q = lane & 3;
    const int g8 = lane >> 2;
    const int lr0 = warp * 16 + g8;
    const int lr1 = lr0 + 8;
    const int qg = q * 8 + g8;  // B-frag word offset (conflict-free)
    const int G0 = ((lr0 >> 5) << 7) + U0 + (lr0 & 31);
    const int G1 = G0 + 8;

    // ---- weights -> registers as tf32 A-fragments ----
    uint32_t w1[64], w2h[64], w2i[64];
#pragma unroll
    for (int kt = 0; kt < 16; ++kt) {
        const int k0 = kt * 8 + q;
        w1[kt * 4 + 0] = tfbits(Whh1[G0 * Ht + k0]);
        w1[kt * 4 + 1] = tfbits(Whh1[G1 * Ht + k0]);
        w1[kt * 4 + 2] = tfbits(Whh1[G0 * Ht + k0 + 4]);
        w1[kt * 4 + 3] = tfbits(Whh1[G1 * Ht + k0 + 4]);
        w2h[kt * 4 + 0] = tfbits(Whh2[G0 * Ht + k0]);
        w2h[kt * 4 + 1] = tfbits(Whh2[G1 * Ht + k0]);
        w2h[kt * 4 + 2] = tfbits(Whh2[G0 * Ht + k0 + 4]);
        w2h[kt * 4 + 3] = tfbits(Whh2[G1 * Ht + k0 + 4]);
        w2i[kt * 4 + 0] = tfbits(Wih2[G0 * Ht + k0]);
        w2i[kt * 4 + 1] = tfbits(Wih2[G1 * Ht + k0]);
        w2i[kt * 4 + 2] = tfbits(Wih2[G0 * Ht + k0 + 4]);
        w2i[kt * 4 + 3] = tfbits(Wih2[G1 * Ht + k0 + 4]);
    }

    // ---- biases / small vectors into SMEM; zero h slots ----
    for (int r = tid; r < 128; r += NTH) {
        const int G = ((r >> 5) << 7) + U0 + (r & 31);
        bs1s[r] = bih1[G] + bhh1[G];
        wxs[r] = Wih1[G];
        bs2s[r] = bih2[G] + bhh2[G];
        wos[r] = Wout[r];
    }
    for (int i = tid; i < 4096; i += NTH) sm[OFF_HT1 + i] = 0.0f;
    if (tid == 0) boS[0] = bout[0];
    if (tid < BC) xS[tid] = x[(bbase + tid) * Tt + 0];  // x(0) -> slot 0
    __syncthreads();
    cl_arrive();
    cl_wait();  // peers' h buffers zeroed

    const uint32_t h1u = s2u(hT1);
    const uint32_t h2u = s2u(hT2);
    const uint32_t p1 = (rank + 1) & 3, p2r = (rank + 2) & 3, p3 = (rank + 3) & 3;
    const float boutr = boS[0];

    // epilogue mapping
    const int bb = tid & 7;
    const int uu = tid >> 3;
    const int hword = (U0 + uu) * 8 + bb;
    const float bA0 = bs1s[0 * 32 + uu], bA1 = bs1s[1 * 32 + uu];
    const float bA2 = bs1s[2 * 32 + uu], bA3 = bs1s[3 * 32 + uu];
    const float wx0 = wxs[0 * 32 + uu], wx1 = wxs[1 * 32 + uu];
    const float wx2 = wxs[2 * 32 + uu], wx3 = wxs[3 * 32 + uu];
    const float bB0 = bs2s[0 * 32 + uu], bB1 = bs2s[1 * 32 + uu];
    const float bB2 = bs2s[2 * 32 + uu], bB3 = bs2s[3 * 32 + uu];

    float c1 = 0.0f, c2 = 0.0f;

    // iteration i: h1(i) -> hT1 slot i&1 ; h2(i-1) -> hT2 slot (i-1)&1
    for (int i = 0; i <= Tt; ++i) {
        const int p = i & 1;
        const int pp = p ^ 1;
        const bool doA = (i < Tt);
        const bool doB = (i > 0);

        const float* h1p = hT1 + pp * 1024;  // h1(i-1)
        const float* h2p = hT2 + p * 1024;   // h2(i-2)

        // ===== phase 1: D1 = Whh1 @ h1(i-1) =====
        if (doA) {
            float d1a[4] = {0, 0, 0, 0}, d1b[4] = {0, 0, 0, 0};
#pragma unroll
            for (int kt = 0; kt < 16; ++kt) {
                const uint32_t b0 = __float_as_uint(h1p[kt * 64 + qg]);
                const uint32_t b1 = __float_as_uint(h1p[kt * 64 + 32 + qg]);
                mma8((kt & 1) ? d1b : d1a, &w1[kt * 4], b0, b1);
            }
            float2* gA2 = reinterpret_cast<float2*>(gbA);
            gA2[lr0 * 4 + q] = make_float2(d1a[0] + d1b[0], d1a[1] + d1b[1]);
            gA2[lr1 * 4 + q] = make_float2(d1a[2] + d1b[2], d1a[3] + d1b[3]);
            __syncthreads();

            // ---- epilogue A: c1/h1(i) -> slot p, push (drain hides in D2) ----
            const float xv = xS[p * 8 + bb];
            const float gi = gbA[(0 * 32 + uu) * 8 + bb] + bA0 + xv * wx0;
            const float gf = gbA[(1 * 32 + uu) * 8 + bb] + bA1 + xv * wx1;
            const float gg = gbA[(2 * 32 + uu) * 8 + bb] + bA2 + xv * wx2;
            const float go = gbA[(3 * 32 + uu) * 8 + bb] + bA3 + xv * wx3;
            c1 = sigf(gf) * c1 + sigf(gi) * tanh_fast(gg);
            const float h1v = to_tf32(sigf(go) * tanh_fast(c1));
            hT1[p * 1024 + hword] = h1v;
            const uint32_t la = h1u + (uint32_t)(p * 1024 + hword) * 4u;
            st_remote(la, p1, h1v);
            st_remote(la, p2r, h1v);
            st_remote(la, p3, h1v);
        }

        // ===== phase 2: D2 = Whh2 @ h2(i-2) + Wih2 @ h1(i-1) =====
        if (doB) {
            float d2a[4] = {0, 0, 0, 0}, d2b[4] = {0, 0, 0, 0};
            float d2c[4] = {0, 0, 0, 0}, d2d[4] = {0, 0, 0, 0};
#pragma unroll
            for (int kt = 0; kt < 16; ++kt) {
                const uint32_t e0 = __float_as_uint(h2p[kt * 64 + qg]);
                const uint32_t e1 = __float_as_uint(h2p[kt * 64 + 32 + qg]);
                const uint32_t b0 = __float_as_uint(h1p[kt * 64 + qg]);
                const uint32_t b1 = __float_as_uint(h1p[kt * 64 + 32 + qg]);
                mma8((kt & 1) ? d2b : d2a, &w2h[kt * 4], e0, e1);
                mma8((kt & 1) ? d2d : d2c, &w2i[kt * 4], b0, b1);
            }
            float2* gB2 = reinterpret_cast<float2*>(gbB);
            gB2[lr0 * 4 + q] =
                make_float2(d2a[0] + d2b[0] + d2c[0] + d2d[0],
                            d2a[1] + d2b[1] + d2c[1] + d2d[1]);
            gB2[lr1 * 4 + q] =
                make_float2(d2a[2] + d2b[2] + d2c[2] + d2d[2],
                            d2a[3] + d2b[3] + d2c[3] + d2d[3]);
            __syncthreads();

            // ---- epilogue B: c2/h2(i-1) -> slot pp, push ----
            const float gi = gbB[(0 * 32 + uu) * 8 + bb] + bB0;
            const float gf = gbB[(1 * 32 + uu) * 8 + bb] + bB1;
            const float gg = gbB[(2 * 32 + uu) * 8 + bb] + bB2;
            const float go = gbB[(3 * 32 + uu) * 8 + bb] + bB3;
            c2 = sigf(gf) * c2 + sigf(gi) * tanh_fast(gg);
            const float h2v = to_tf32(sigf(go) * tanh_fast(c2));
            hT2[pp * 1024 + hword] = h2v;
            const uint32_t la = h2u + (uint32_t)(pp * 1024 + hword) * 4u;
            st_remote(la, p1, h2v);
            st_remote(la, p2r, h2v);
            st_remote(la, p3, h2v);
        }

        // ===== single cluster barrier: h1(i) + h2(i-1) published =====
        cl_arrive();
        // x prefetch + staging for next iteration in the arrive->wait gap
        if (tid < BC && doA) {
            xS[pp * 8 + tid] =
                (i + 1 < Tt) ? x[(bbase + tid) * Tt + (i + 1)] : 0.0f;
        }
        cl_wait();

        // ===== output(i-1): warps 6,7 (overlaps next iteration's MMA) =====
        if (doB && warp >= 6) {
            const int bl = rank * 2 + (warp - 6);
            const float* h2c = hT2 + pp * 1024;
            float s = 0.0f;
#pragma unroll
            for (int j = 0; j < 4; ++j) {
                const int k = lane + 32 * j;
                s += h2c[k * 8 + bl] * wos[k];
            }
            s += __shfl_xor_sync(0xffffffffu, s, 16);
            s += __shfl_xor_sync(0xffffffffu, s, 8);
            s += __shfl_xor_sync(0xffffffffu, s, 4);
            s += __shfl_xor_sync(0xffffffffu, s, 2);
            s += __shfl_xor_sync(0xffffffffu, s, 1);
            if (lane == 0) out[(bbase + bl) * Tt + (i - 1)] = s + boutr;
        }
    }

    // exit safety
    cl_arrive();
    cl_wait();
}

}  // namespace

extern "C" void kernel_launch(void* const* d_in, const int* in_sizes, int n_in,
                              void* d_out, int out_size) {
    (void)in_sizes;
    (void)n_in;
    (void)out_size;
    const float* x = (const float*)d_in[0];
    const float* Wih1 = (const float*)d_in[1];
    const float* Whh1 = (const float*)d_in[2];
    const float* bih1 = (const float*)d_in[3];
    const float* bhh1 = (const float*)d_in[4];
    const float* Wih2 = (const float*)d_in[5];
    const float* Whh2 = (const float*)d_in[6];
    const float* bih2 = (const float*)d_in[7];
    const float* bhh2 = (const float*)d_in[8];
    const float* Wout = (const float*)d_in[9];
    const float* bout = (const float*)d_in[10];
    float* out = (float*)d_out;

    cudaFuncSetAttribute(lstm_mma_kernel,
                         cudaFuncAttributeMaxDynamicSharedMemorySize, SM_BYTES);

    cudaLaunchConfig_t cfg = {};
    cfg.gridDim = dim3((Bt / BC) * CL, 1, 1);  // 128 CTAs = 32 clusters of 4
    cfg.blockDim = dim3(NTH, 1, 1);
    cfg.dynamicSmemBytes = SM_BYTES;
    cfg.stream = 0;
    cudaLaunchAttribute attrs[1];
    attrs[0].id = cudaLaunchAttributeClusterDimension;
    attrs[0].val.clusterDim.x = CL;
    attrs[0].val.clusterDim.y = 1;
    attrs[0].val.clusterDim.z = 1;
    cfg.attrs = attrs;
    cfg.numAttrs = 1;

    cudaLaunchKernelEx(&cfg, lstm_mma_kernel, x, Wih1, Whh1, bih1, bhh1, Wih2,
                       Whh2, bih2, bhh2, Wout, bout, out);
}

// round 14
// speedup vs baseline: 1.5030x; 1.2783x over previous
#include <cuda_runtime.h>
#include <cuda_fp16.h>
#include <cstdint>

// LSTMPredictor: B=256, T=1024, H=128, 2-layer LSTM + linear head.
// 32 clusters x 4 CTAs x 256 threads. Layer-pipelined: iteration i computes
// h1(i) and h2(i-1); ONE cluster barrier per iteration (R12 structure).
// R13: fp16 mma.sync m16n8k16 (fp32 accumulate). fp16 carries the same
// 11-bit significand as tf32 -> same accuracy, but half the MMA count,
// half the h-vector LDS, half the DSMEM push bytes.
// h stored as half2-packed [k/2][batch] words, double-buffered.

namespace {

constexpr int Bt = 256;
constexpr int Tt = 1024;
constexpr int Ht = 128;
constexpr int CL = 4;
constexpr int BC = 8;
constexpr int NTH = 256;

// smem (32-bit words)
constexpr int OFF_HT1 = 0;      // h1: 2 slot x 64 kp x 8 b half2 = 1024 words
constexpr int OFF_HT2 = 1024;   // h2
constexpr int OFF_GA  = 2048;   // gates1 staging [128 r][8 b] fp32
constexpr int OFF_GB  = 3072;   // gates2 staging
constexpr int OFF_BS1 = 4096;   // 128
constexpr int OFF_WX  = 4224;   // 128
constexpr int OFF_BS2 = 4352;   // 128
constexpr int OFF_WO  = 4480;   // 128
constexpr int OFF_X   = 4608;   // 2 slot x 8
constexpr int OFF_BO  = 4624;   // 1 (+pad)
constexpr int SM_FLOATS = 4628;
constexpr int SM_BYTES = SM_FLOATS * 4;  // ~18.5 KB

__device__ __forceinline__ uint32_t s2u(const void* p) {
    return (uint32_t)__cvta_generic_to_shared(p);
}
__device__ __forceinline__ uint32_t pkh2(float a, float b) {
    __half2 h = __halves2half2(__float2half_rn(a), __float2half_rn(b));
    return *reinterpret_cast<uint32_t*>(&h);
}
// m16n8k16 row.col f16 mma, fp32 accum
__device__ __forceinline__ void mma16(float* d, const uint32_t* a, uint32_t b0,
                                      uint32_t b1) {
    asm volatile(
        "mma.sync.aligned.m16n8k16.row.col.f32.f16.f16.f32 "
        "{%0,%1,%2,%3}, {%4,%5,%6,%7}, {%8,%9}, {%0,%1,%2,%3};"
        : "+f"(d[0]), "+f"(d[1]), "+f"(d[2]), "+f"(d[3])
        : "r"(a[0]), "r"(a[1]), "r"(a[2]), "r"(a[3]), "r"(b0), "r"(b1));
}
__device__ __forceinline__ void st_remote_h(uint32_t laddr, uint32_t peer,
                                            unsigned short v) {
    uint32_t r;
    asm("mapa.shared::cluster.u32 %0, %1, %2;" : "=r"(r) : "r"(laddr), "r"(peer));
    asm volatile("st.shared::cluster.u16 [%0], %1;" ::"r"(r), "h"(v) : "memory");
}
__device__ __forceinline__ void cl_arrive() {
    asm volatile("barrier.cluster.arrive.aligned;" ::: "memory");
}
__device__ __forceinline__ void cl_wait() {
    asm volatile("barrier.cluster.wait.aligned;" ::: "memory");
}
__device__ __forceinline__ float sigf(float x) {
    return __fdividef(1.0f, 1.0f + __expf(-x));
}
__device__ __forceinline__ float tanh_fast(float x) {
    return __fdividef(2.0f, 1.0f + __expf(-2.0f * x)) - 1.0f;
}

__global__ void __launch_bounds__(NTH, 1) lstm_mma_kernel(
    const float* __restrict__ x, const float* __restrict__ Wih1,
    const float* __restrict__ Whh1, const float* __restrict__ bih1,
    const float* __restrict__ bhh1, const float* __restrict__ Wih2,
    const float* __restrict__ Whh2, const float* __restrict__ bih2,
    const float* __restrict__ bhh2, const float* __restrict__ Wout,
    const float* __restrict__ bout, float* __restrict__ out) {
    extern __shared__ float sm[];
    uint32_t* hH1 = reinterpret_cast<uint32_t*>(sm + OFF_HT1);
    uint32_t* hH2 = reinterpret_cast<uint32_t*>(sm + OFF_HT2);
    float* gbA = sm + OFF_GA;
    float* gbB = sm + OFF_GB;
    float* bs1s = sm + OFF_BS1;
    float* wxs = sm + OFF_WX;
    float* bs2s = sm + OFF_BS2;
    float* wos = sm + OFF_WO;
    float* xS = sm + OFF_X;
    float* boS = sm + OFF_BO;

    const int tid = threadIdx.x;
    const int lane = tid & 31;
    const int warp = tid >> 5;
    const int rank = blockIdx.x & 3;
    const int bbase = (blockIdx.x >> 2) * BC;
    const int U0 = rank * 32;

    // ---- MMA fragment coordinates (m16n8k16) ----
    const int q = lane & 3;          // threadID in group
    const int g8 = lane >> 2;        // group 0..7
    const int lr0 = warp * 16 + g8;  // local rows lr0, lr0+8
    const int lr1 = lr0 + 8;
    const int qg = q * 8 + g8;       // B-frag word offset within kt block
    const int G0 = ((lr0 >> 5) << 7) + U0 + (lr0 & 31);
    const int G1 = G0 + 8;

    // ---- weights -> registers as fp16 A-fragments (8 kt x 4 regs each) ----
    uint32_t w1[32], w2h[32], w2i[32];
#pragma unroll
    for (int kt = 0; kt < 8; ++kt) {
        const int k0 = kt * 16 + q * 2;
        w1[kt * 4 + 0] = pkh2(Whh1[G0 * Ht + k0], Whh1[G0 * Ht + k0 + 1]);
        w1[kt * 4 + 1] = pkh2(Whh1[G1 * Ht + k0], Whh1[G1 * Ht + k0 + 1]);
        w1[kt * 4 + 2] = pkh2(Whh1[G0 * Ht + k0 + 8], Whh1[G0 * Ht + k0 + 9]);
        w1[kt * 4 + 3] = pkh2(Whh1[G1 * Ht + k0 + 8], Whh1[G1 * Ht + k0 + 9]);
        w2h[kt * 4 + 0] = pkh2(Whh2[G0 * Ht + k0], Whh2[G0 * Ht + k0 + 1]);
        w2h[kt * 4 + 1] = pkh2(Whh2[G1 * Ht + k0], Whh2[G1 * Ht + k0 + 1]);
        w2h[kt * 4 + 2] = pkh2(Whh2[G0 * Ht + k0 + 8], Whh2[G0 * Ht + k0 + 9]);
        w2h[kt * 4 + 3] = pkh2(Whh2[G1 * Ht + k0 + 8], Whh2[G1 * Ht + k0 + 9]);
        w2i[kt * 4 + 0] = pkh2(Wih2[G0 * Ht + k0], Wih2[G0 * Ht + k0 + 1]);
        w2i[kt * 4 + 1] = pkh2(Wih2[G1 * Ht + k0], Wih2[G1 * Ht + k0 + 1]);
        w2i[kt * 4 + 2] = pkh2(Wih2[G0 * Ht + k0 + 8], Wih2[G0 * Ht + k0 + 9]);
        w2i[kt * 4 + 3] = pkh2(Wih2[G1 * Ht + k0 + 8], Wih2[G1 * Ht + k0 + 9]);
    }

    // ---- biases / small vectors into SMEM; zero h slots ----
    for (int r = tid; r < 128; r += NTH) {
        const int G = ((r >> 5) << 7) + U0 + (r & 31);
        bs1s[r] = bih1[G] + bhh1[G];
        wxs[r] = Wih1[G];
        bs2s[r] = bih2[G] + bhh2[G];
        wos[r] = Wout[r];
    }
    for (int i = tid; i < 2048; i += NTH) sm[OFF_HT1 + i] = 0.0f;  // h tiles
    if (tid == 0) boS[0] = bout[0];
    if (tid < BC) xS[tid] = x[(bbase + tid) * Tt + 0];  // x(0) -> slot 0
    __syncthreads();
    cl_arrive();
    cl_wait();  // peers' h buffers zeroed

    const uint32_t h1u = s2u(hH1);
    const uint32_t h2u = s2u(hH2);
    const uint32_t p1 = (rank + 1) & 3, p2r = (rank + 2) & 3, p3 = (rank + 3) & 3;
    const float boutr = boS[0];

    // epilogue mapping: bb = tid&7, unit gU = U0 + (tid>>3)
    const int bb = tid & 7;
    const int uu = tid >> 3;
    const int gU = U0 + uu;
    // byte offset of this thread's half within an h slot (slot = 2048 B)
    const uint32_t hbyte = (uint32_t)(((gU >> 1) * 8 + bb) * 4 + (gU & 1) * 2);
    const float bA0 = bs1s[0 * 32 + uu], bA1 = bs1s[1 * 32 + uu];
    const float bA2 = bs1s[2 * 32 + uu], bA3 = bs1s[3 * 32 + uu];
    const float wx0 = wxs[0 * 32 + uu], wx1 = wxs[1 * 32 + uu];
    const float wx2 = wxs[2 * 32 + uu], wx3 = wxs[3 * 32 + uu];
    const float bB0 = bs2s[0 * 32 + uu], bB1 = bs2s[1 * 32 + uu];
    const float bB2 = bs2s[2 * 32 + uu], bB3 = bs2s[3 * 32 + uu];
    // output-head weights (warps 6,7): lane covers kp = lane, lane+32
    const float wo0 = wos[2 * lane], wo1 = wos[2 * lane + 1];
    const float wo2 = wos[2 * lane + 64], wo3 = wos[2 * lane + 65];

    float c1 = 0.0f, c2 = 0.0f;

    // iteration i: h1(i) -> hH1 slot i&1 ; h2(i-1) -> hH2 slot (i-1)&1
    for (int i = 0; i <= Tt; ++i) {
        const int p = i & 1;
        const int pp = p ^ 1;
        const bool doA = (i < Tt);
        const bool doB = (i > 0);

        const uint32_t* h1p = hH1 + pp * 512;  // h1(i-1)
        const uint32_t* h2p = hH2 + p * 512;   // h2(i-2)

        // ===== phase 1: D1 = Whh1 @ h1(i-1) =====
        if (doA) {
            float d1a[4] = {0, 0, 0, 0}, d1b[4] = {0, 0, 0, 0};
#pragma unroll
            for (int kt = 0; kt < 8; ++kt) {
                const uint32_t b0 = h1p[kt * 64 + qg];
                const uint32_t b1 = h1p[kt * 64 + 32 + qg];
                mma16((kt & 1) ? d1b : d1a, &w1[kt * 4], b0, b1);
            }
            float2* gA2 = reinterpret_cast<float2*>(gbA);
            gA2[lr0 * 4 + q] = make_float2(d1a[0] + d1b[0], d1a[1] + d1b[1]);
            gA2[lr1 * 4 + q] = make_float2(d1a[2] + d1b[2], d1a[3] + d1b[3]);
            __syncthreads();

            // ---- epilogue A: c1/h1(i) -> slot p, push (drain hides in D2) ----
            const float xv = xS[p * 8 + bb];
            const float gi = gbA[(0 * 32 + uu) * 8 + bb] + bA0 + xv * wx0;
            const float gf = gbA[(1 * 32 + uu) * 8 + bb] + bA1 + xv * wx1;
            const float gg = gbA[(2 * 32 + uu) * 8 + bb] + bA2 + xv * wx2;
            const float go = gbA[(3 * 32 + uu) * 8 + bb] + bA3 + xv * wx3;
            c1 = sigf(gf) * c1 + sigf(gi) * tanh_fast(gg);
            const float h1f = sigf(go) * tanh_fast(c1);
            const __half h1h = __float2half_rn(h1f);
            const unsigned short h1b = *reinterpret_cast<const unsigned short*>(&h1h);
            const uint32_t la = h1u + (uint32_t)p * 2048u + hbyte;
            asm volatile("st.shared.u16 [%0], %1;" ::"r"(la), "h"(h1b) : "memory");
            st_remote_h(la, p1, h1b);
            st_remote_h(la, p2r, h1b);
            st_remote_h(la, p3, h1b);
        }

        // ===== phase 2: D2 = Whh2 @ h2(i-2) + Wih2 @ h1(i-1) =====
        if (doB) {
            float d2a[4] = {0, 0, 0, 0}, d2b[4] = {0, 0, 0, 0};
            float d2c[4] = {0, 0, 0, 0}, d2d[4] = {0, 0, 0, 0};
#pragma unroll
            for (int kt = 0; kt < 8; ++kt) {
                const uint32_t e0 = h2p[kt * 64 + qg];
                const uint32_t e1 = h2p[kt * 64 + 32 + qg];
                const uint32_t b0 = h1p[kt * 64 + qg];
                const uint32_t b1 = h1p[kt * 64 + 32 + qg];
                mma16((kt & 1) ? d2b : d2a, &w2h[kt * 4], e0, e1);
                mma16((kt & 1) ? d2d : d2c, &w2i[kt * 4], b0, b1);
            }
            float2* gB2 = reinterpret_cast<float2*>(gbB);
            gB2[lr0 * 4 + q] =
                make_float2(d2a[0] + d2b[0] + d2c[0] + d2d[0],
                            d2a[1] + d2b[1] + d2c[1] + d2d[1]);
            gB2[lr1 * 4 + q] =
                make_float2(d2a[2] + d2b[2] + d2c[2] + d2d[2],
                            d2a[3] + d2b[3] + d2c[3] + d2d[3]);
            __syncthreads();

            // ---- epilogue B: c2/h2(i-1) -> slot pp, push ----
            const float gi = gbB[(0 * 32 + uu) * 8 + bb] + bB0;
            const float gf = gbB[(1 * 32 + uu) * 8 + bb] + bB1;
            const float gg = gbB[(2 * 32 + uu) * 8 + bb] + bB2;
            const float go = gbB[(3 * 32 + uu) * 8 + bb] + bB3;
            c2 = sigf(gf) * c2 + sigf(gi) * tanh_fast(gg);
            const float h2f = sigf(go) * tanh_fast(c2);
            const __half h2h = __float2half_rn(h2f);
            const unsigned short h2b = *reinterpret_cast<const unsigned short*>(&h2h);
            const uint32_t la = h2u + (uint32_t)pp * 2048u + hbyte;
            asm volatile("st.shared.u16 [%0], %1;" ::"r"(la), "h"(h2b) : "memory");
            st_remote_h(la, p1, h2b);
            st_remote_h(la, p2r, h2b);
            st_remote_h(la, p3, h2b);
        }

        // ===== single cluster barrier: h1(i) + h2(i-1) published =====
        cl_arrive();
        // x prefetch + staging for next iteration in the arrive->wait gap
        if (tid < BC && doA) {
            xS[pp * 8 + tid] =
                (i + 1 < Tt) ? x[(bbase + tid) * Tt + (i + 1)] : 0.0f;
        }
        cl_wait();

        // ===== output(i-1): warps 6,7 (overlaps next iteration's MMA) =====
        if (doB && warp >= 6) {
            const int bl = rank * 2 + (warp - 6);
            const uint32_t* h2c = hH2 + pp * 512;
            const __half2 ha = *reinterpret_cast<const __half2*>(&h2c[lane * 8 + bl]);
            const __half2 hb =
                *reinterpret_cast<const __half2*>(&h2c[(lane + 32) * 8 + bl]);
            const float2 fa = __half22float2(ha);
            const float2 fb = __half22float2(hb);
            float s = fa.x * wo0 + fa.y * wo1 + fb.x * wo2 + fb.y * wo3;
            s += __shfl_xor_sync(0xffffffffu, s, 16);
            s += __shfl_xor_sync(0xffffffffu, s, 8);
            s += __shfl_xor_sync(0xffffffffu, s, 4);
            s += __shfl_xor_sync(0xffffffffu, s, 2);
            s += __shfl_xor_sync(0xffffffffu, s, 1);
            if (lane == 0) out[(bbase + bl) * Tt + (i - 1)] = s + boutr;
        }
    }

    // exit safety
    cl_arrive();
    cl_wait();
}

}  // namespace

extern "C" void kernel_launch(void* const* d_in, const int* in_sizes, int n_in,
                              void* d_out, int out_size) {
    (void)in_sizes;
    (void)n_in;
    (void)out_size;
    const float* x = (const float*)d_in[0];
    const float* Wih1 = (const float*)d_in[1];
    const float* Whh1 = (const float*)d_in[2];
    const float* bih1 = (const float*)d_in[3];
    const float* bhh1 = (const float*)d_in[4];
    const float* Wih2 = (const float*)d_in[5];
    const float* Whh2 = (const float*)d_in[6];
    const float* bih2 = (const float*)d_in[7];
    const float* bhh2 = (const float*)d_in[8];
    const float* Wout = (const float*)d_in[9];
    const float* bout = (const float*)d_in[10];
    float* out = (float*)d_out;

    cudaFuncSetAttribute(lstm_mma_kernel,
                         cudaFuncAttributeMaxDynamicSharedMemorySize, SM_BYTES);

    cudaLaunchConfig_t cfg = {};
    cfg.gridDim = dim3((Bt / BC) * CL, 1, 1);  // 128 CTAs = 32 clusters of 4
    cfg.blockDim = dim3(NTH, 1, 1);
    cfg.dynamicSmemBytes = SM_BYTES;
    cfg.stream = 0;
    cudaLaunchAttribute attrs[1];
    attrs[0].id = cudaLaunchAttributeClusterDimension;
    attrs[0].val.clusterDim.x = CL;
    attrs[0].val.clusterDim.y = 1;
    attrs[0].val.clusterDim.z = 1;
    cfg.attrs = attrs;
    cfg.numAttrs = 1;

    cudaLaunchKernelEx(&cfg, lstm_mma_kernel, x, Wih1, Whh1, bih1, bhh1, Wih2,
                       Whh2, bih2, bhh2, Wout, bout, out);
}

// round 15
// speedup vs baseline: 1.6259x; 1.0818x over previous
#include <cuda_runtime.h>
#include <cuda_fp16.h>
#include <cstdint>

// LSTMPredictor: B=256, T=1024, H=128, 2-layer LSTM + linear head.
// 32 clusters x 4 CTAs x 256 threads. Layer-pipelined: iteration i computes
// h1(i) and h2(i-1); ONE cluster barrier per iteration. fp16 mma.sync
// m16n8k16 (fp32 accum), weights register-resident, h half2-packed [k/2][b].
// R14: merged iteration body. Phase-2 inputs (h2(i-2), h1(i-1)) are available
// at iteration start, so all 24 MMAs issue together (6 accumulator chains,
// shared h1 B-fragments), ONE __syncthreads, and both gate epilogues run
// back-to-back (their MUFU chains overlap via ILP). Both DSMEM push drains
// overlap before the single arrive.

namespace {

constexpr int Bt = 256;
constexpr int Tt = 1024;
constexpr int Ht = 128;
constexpr int CL = 4;
constexpr int BC = 8;
constexpr int NTH = 256;

// smem (32-bit words)
constexpr int OFF_HT1 = 0;      // h1: 2 slot x 64 kp x 8 b half2 = 1024 words
constexpr int OFF_HT2 = 1024;   // h2
constexpr int OFF_GA  = 2048;   // gates1 staging [128 r][8 b] fp32
constexpr int OFF_GB  = 3072;   // gates2 staging
constexpr int OFF_BS1 = 4096;   // 128
constexpr int OFF_WX  = 4224;   // 128
constexpr int OFF_BS2 = 4352;   // 128
constexpr int OFF_WO  = 4480;   // 128
constexpr int OFF_X   = 4608;   // 2 slot x 8
constexpr int OFF_BO  = 4624;   // 1 (+pad)
constexpr int SM_FLOATS = 4628;
constexpr int SM_BYTES = SM_FLOATS * 4;  // ~18.5 KB

__device__ __forceinline__ uint32_t s2u(const void* p) {
    return (uint32_t)__cvta_generic_to_shared(p);
}
__device__ __forceinline__ uint32_t pkh2(float a, float b) {
    __half2 h = __halves2half2(__float2half_rn(a), __float2half_rn(b));
    return *reinterpret_cast<uint32_t*>(&h);
}
// m16n8k16 row.col f16 mma, fp32 accum
__device__ __forceinline__ void mma16(float* d, const uint32_t* a, uint32_t b0,
                                      uint32_t b1) {
    asm volatile(
        "mma.sync.aligned.m16n8k16.row.col.f32.f16.f16.f32 "
        "{%0,%1,%2,%3}, {%4,%5,%6,%7}, {%8,%9}, {%0,%1,%2,%3};"
        : "+f"(d[0]), "+f"(d[1]), "+f"(d[2]), "+f"(d[3])
        : "r"(a[0]), "r"(a[1]), "r"(a[2]), "r"(a[3]), "r"(b0), "r"(b1));
}
__device__ __forceinline__ void st_remote_h(uint32_t laddr, uint32_t peer,
                                            unsigned short v) {
    uint32_t r;
    asm("mapa.shared::cluster.u32 %0, %1, %2;" : "=r"(r) : "r"(laddr), "r"(peer));
    asm volatile("st.shared::cluster.u16 [%0], %1;" ::"r"(r), "h"(v) : "memory");
}
__device__ __forceinline__ void cl_arrive() {
    asm volatile("barrier.cluster.arrive.aligned;" ::: "memory");
}
__device__ __forceinline__ void cl_wait() {
    asm volatile("barrier.cluster.wait.aligned;" ::: "memory");
}
__device__ __forceinline__ float sigf(float x) {
    return __fdividef(1.0f, 1.0f + __expf(-x));
}
__device__ __forceinline__ float tanh_fast(float x) {
    return __fdividef(2.0f, 1.0f + __expf(-2.0f * x)) - 1.0f;
}

__global__ void __launch_bounds__(NTH, 1) lstm_mma_kernel(
    const float* __restrict__ x, const float* __restrict__ Wih1,
    const float* __restrict__ Whh1, const float* __restrict__ bih1,
    const float* __restrict__ bhh1, const float* __restrict__ Wih2,
    const float* __restrict__ Whh2, const float* __restrict__ bih2,
    const float* __restrict__ bhh2, const float* __restrict__ Wout,
    const float* __restrict__ bout, float* __restrict__ out) {
    extern __shared__ float sm[];
    uint32_t* hH1 = reinterpret_cast<uint32_t*>(sm + OFF_HT1);
    uint32_t* hH2 = reinterpret_cast<uint32_t*>(sm + OFF_HT2);
    float* gbA = sm + OFF_GA;
    float* gbB = sm + OFF_GB;
    float* bs1s = sm + OFF_BS1;
    float* wxs = sm + OFF_WX;
    float* bs2s = sm + OFF_BS2;
    float* wos = sm + OFF_WO;
    float* xS = sm + OFF_X;
    float* boS = sm + OFF_BO;

    const int tid = threadIdx.x;
    const int lane = tid & 31;
    const int warp = tid >> 5;
    const int rank = blockIdx.x & 3;
    const int bbase = (blockIdx.x >> 2) * BC;
    const int U0 = rank * 32;

    // ---- MMA fragment coordinates (m16n8k16) ----
    const int q = lane & 3;
    const int g8 = lane >> 2;
    const int lr0 = warp * 16 + g8;
    const int lr1 = lr0 + 8;
    const int qg = q * 8 + g8;  // B-frag word offset within kt block
    const int G0 = ((lr0 >> 5) << 7) + U0 + (lr0 & 31);
    const int G1 = G0 + 8;

    // ---- weights -> registers as fp16 A-fragments (8 kt x 4 regs each) ----
    uint32_t w1[32], w2h[32], w2i[32];
#pragma unroll
    for (int kt = 0; kt < 8; ++kt) {
        const int k0 = kt * 16 + q * 2;
        w1[kt * 4 + 0] = pkh2(Whh1[G0 * Ht + k0], Whh1[G0 * Ht + k0 + 1]);
        w1[kt * 4 + 1] = pkh2(Whh1[G1 * Ht + k0], Whh1[G1 * Ht + k0 + 1]);
        w1[kt * 4 + 2] = pkh2(Whh1[G0 * Ht + k0 + 8], Whh1[G0 * Ht + k0 + 9]);
        w1[kt * 4 + 3] = pkh2(Whh1[G1 * Ht + k0 + 8], Whh1[G1 * Ht + k0 + 9]);
        w2h[kt * 4 + 0] = pkh2(Whh2[G0 * Ht + k0], Whh2[G0 * Ht + k0 + 1]);
        w2h[kt * 4 + 1] = pkh2(Whh2[G1 * Ht + k0], Whh2[G1 * Ht + k0 + 1]);
        w2h[kt * 4 + 2] = pkh2(Whh2[G0 * Ht + k0 + 8], Whh2[G0 * Ht + k0 + 9]);
        w2h[kt * 4 + 3] = pkh2(Whh2[G1 * Ht + k0 + 8], Whh2[G1 * Ht + k0 + 9]);
        w2i[kt * 4 + 0] = pkh2(Wih2[G0 * Ht + k0], Wih2[G0 * Ht + k0 + 1]);
        w2i[kt * 4 + 1] = pkh2(Wih2[G1 * Ht + k0], Wih2[G1 * Ht + k0 + 1]);
        w2i[kt * 4 + 2] = pkh2(Wih2[G0 * Ht + k0 + 8], Wih2[G0 * Ht + k0 + 9]);
        w2i[kt * 4 + 3] = pkh2(Wih2[G1 * Ht + k0 + 8], Wih2[G1 * Ht + k0 + 9]);
    }

    // ---- biases / small vectors into SMEM; zero h slots ----
    for (int r = tid; r < 128; r += NTH) {
        const int G = ((r >> 5) << 7) + U0 + (r & 31);
        bs1s[r] = bih1[G] + bhh1[G];
        wxs[r] = Wih1[G];
        bs2s[r] = bih2[G] + bhh2[G];
        wos[r] = Wout[r];
    }
    for (int i = tid; i < 2048; i += NTH) sm[OFF_HT1 + i] = 0.0f;  // h tiles
    if (tid == 0) boS[0] = bout[0];
    if (tid < BC) xS[tid] = x[(bbase + tid) * Tt + 0];  // x(0) -> slot 0
    __syncthreads();
    cl_arrive();
    cl_wait();  // peers' h buffers zeroed

    const uint32_t h1u = s2u(hH1);
    const uint32_t h2u = s2u(hH2);
    const uint32_t p1 = (rank + 1) & 3, p2r = (rank + 2) & 3, p3 = (rank + 3) & 3;
    const float boutr = boS[0];

    // epilogue mapping: bb = tid&7, unit gU = U0 + (tid>>3)
    const int bb = tid & 7;
    const int uu = tid >> 3;
    const int gU = U0 + uu;
    const uint32_t hbyte = (uint32_t)(((gU >> 1) * 8 + bb) * 4 + (gU & 1) * 2);
    const float bA0 = bs1s[0 * 32 + uu], bA1 = bs1s[1 * 32 + uu];
    const float bA2 = bs1s[2 * 32 + uu], bA3 = bs1s[3 * 32 + uu];
    const float wx0 = wxs[0 * 32 + uu], wx1 = wxs[1 * 32 + uu];
    const float wx2 = wxs[2 * 32 + uu], wx3 = wxs[3 * 32 + uu];
    const float bB0 = bs2s[0 * 32 + uu], bB1 = bs2s[1 * 32 + uu];
    const float bB2 = bs2s[2 * 32 + uu], bB3 = bs2s[3 * 32 + uu];
    // output-head weights (warps 6,7)
    const float wo0 = wos[2 * lane], wo1 = wos[2 * lane + 1];
    const float wo2 = wos[2 * lane + 64], wo3 = wos[2 * lane + 65];

    float c1 = 0.0f, c2 = 0.0f;

    // iteration i: h1(i) -> hH1 slot i&1 ; h2(i-1) -> hH2 slot (i-1)&1
    for (int i = 0; i <= Tt; ++i) {
        const int p = i & 1;
        const int pp = p ^ 1;
        const bool doA = (i < Tt);
        const bool doB = (i > 0);

        const uint32_t* h1p = hH1 + pp * 512;  // h1(i-1)
        const uint32_t* h2p = hH2 + p * 512;   // h2(i-2)

        // ===== all MMAs up front: D1 = W1@h1 ; D2 = W2h@h2 + W2i@h1 =====
        float d1a[4] = {0, 0, 0, 0}, d1b[4] = {0, 0, 0, 0};
        float d2a[4] = {0, 0, 0, 0}, d2b[4] = {0, 0, 0, 0};
        float d2c[4] = {0, 0, 0, 0}, d2d[4] = {0, 0, 0, 0};
        if (doA && doB) {
#pragma unroll
            for (int kt = 0; kt < 8; ++kt) {
                const uint32_t b0 = h1p[kt * 64 + qg];
                const uint32_t b1 = h1p[kt * 64 + 32 + qg];
                const uint32_t e0 = h2p[kt * 64 + qg];
                const uint32_t e1 = h2p[kt * 64 + 32 + qg];
                mma16((kt & 1) ? d1b : d1a, &w1[kt * 4], b0, b1);
                mma16((kt & 1) ? d2b : d2a, &w2h[kt * 4], e0, e1);
                mma16((kt & 1) ? d2d : d2c, &w2i[kt * 4], b0, b1);
            }
        } else if (doA) {  // i == 0
#pragma unroll
            for (int kt = 0; kt < 8; ++kt) {
                const uint32_t b0 = h1p[kt * 64 + qg];
                const uint32_t b1 = h1p[kt * 64 + 32 + qg];
                mma16((kt & 1) ? d1b : d1a, &w1[kt * 4], b0, b1);
            }
        } else {  // i == Tt
#pragma unroll
            for (int kt = 0; kt < 8; ++kt) {
                const uint32_t b0 = h1p[kt * 64 + qg];
                const uint32_t b1 = h1p[kt * 64 + 32 + qg];
                const uint32_t e0 = h2p[kt * 64 + qg];
                const uint32_t e1 = h2p[kt * 64 + 32 + qg];
                mma16((kt & 1) ? d2b : d2a, &w2h[kt * 4], e0, e1);
                mma16((kt & 1) ? d2d : d2c, &w2i[kt * 4], b0, b1);
            }
        }
        // stage both gate tiles, then ONE sync
        if (doA) {
            float2* gA2 = reinterpret_cast<float2*>(gbA);
            gA2[lr0 * 4 + q] = make_float2(d1a[0] + d1b[0], d1a[1] + d1b[1]);
            gA2[lr1 * 4 + q] = make_float2(d1a[2] + d1b[2], d1a[3] + d1b[3]);
        }
        if (doB) {
            float2* gB2 = reinterpret_cast<float2*>(gbB);
            gB2[lr0 * 4 + q] =
                make_float2(d2a[0] + d2b[0] + d2c[0] + d2d[0],
                            d2a[1] + d2b[1] + d2c[1] + d2d[1]);
            gB2[lr1 * 4 + q] =
                make_float2(d2a[2] + d2b[2] + d2c[2] + d2d[2],
                            d2a[3] + d2b[3] + d2c[3] + d2d[3]);
        }
        __syncthreads();

        // ===== both epilogues back-to-back (MUFU chains overlap via ILP) ====
        if (doA) {
            const float xv = xS[p * 8 + bb];
            const float gi = gbA[(0 * 32 + uu) * 8 + bb] + bA0 + xv * wx0;
            const float gf = gbA[(1 * 32 + uu) * 8 + bb] + bA1 + xv * wx1;
            const float gg = gbA[(2 * 32 + uu) * 8 + bb] + bA2 + xv * wx2;
            const float go = gbA[(3 * 32 + uu) * 8 + bb] + bA3 + xv * wx3;
            c1 = sigf(gf) * c1 + sigf(gi) * tanh_fast(gg);
            const float h1f = sigf(go) * tanh_fast(c1);
            const __half h1h = __float2half_rn(h1f);
            const unsigned short h1b =
                *reinterpret_cast<const unsigned short*>(&h1h);
            const uint32_t la = h1u + (uint32_t)p * 2048u + hbyte;
            asm volatile("st.shared.u16 [%0], %1;" ::"r"(la), "h"(h1b)
                         : "memory");
            st_remote_h(la, p1, h1b);
            st_remote_h(la, p2r, h1b);
            st_remote_h(la, p3, h1b);
        }
        if (doB) {
            const float gi = gbB[(0 * 32 + uu) * 8 + bb] + bB0;
            const float gf = gbB[(1 * 32 + uu) * 8 + bb] + bB1;
            const float gg = gbB[(2 * 32 + uu) * 8 + bb] + bB2;
            const float go = gbB[(3 * 32 + uu) * 8 + bb] + bB3;
            c2 = sigf(gf) * c2 + sigf(gi) * tanh_fast(gg);
            const float h2f = sigf(go) * tanh_fast(c2);
            const __half h2h = __float2half_rn(h2f);
            const unsigned short h2b =
                *reinterpret_cast<const unsigned short*>(&h2h);
            const uint32_t la = h2u + (uint32_t)pp * 2048u + hbyte;
            asm volatile("st.shared.u16 [%0], %1;" ::"r"(la), "h"(h2b)
                         : "memory");
            st_remote_h(la, p1, h2b);
            st_remote_h(la, p2r, h2b);
            st_remote_h(la, p3, h2b);
        }

        // ===== single cluster barrier: h1(i) + h2(i-1) published =====
        cl_arrive();
        if (tid < BC && doA) {  // x prefetch in the arrive->wait gap
            xS[pp * 8 + tid] =
                (i + 1 < Tt) ? x[(bbase + tid) * Tt + (i + 1)] : 0.0f;
        }
        cl_wait();

        // ===== output(i-1): warps 6,7 (overlaps next iteration's MMA) =====
        if (doB && warp >= 6) {
            const int bl = rank * 2 + (warp - 6);
            const uint32_t* h2c = hH2 + pp * 512;
            const __half2 ha =
                *reinterpret_cast<const __half2*>(&h2c[lane * 8 + bl]);
            const __half2 hb =
                *reinterpret_cast<const __half2*>(&h2c[(lane + 32) * 8 + bl]);
            const float2 fa = __half22float2(ha);
            const float2 fb = __half22float2(hb);
            float s = fa.x * wo0 + fa.y * wo1 + fb.x * wo2 + fb.y * wo3;
            s += __shfl_xor_sync(0xffffffffu, s, 16);
            s += __shfl_xor_sync(0xffffffffu, s, 8);
            s += __shfl_xor_sync(0xffffffffu, s, 4);
            s += __shfl_xor_sync(0xffffffffu, s, 2);
            s += __shfl_xor_sync(0xffffffffu, s, 1);
            if (lane == 0) out[(bbase + bl) * Tt + (i - 1)] = s + boutr;
        }
    }

    // exit safety
    cl_arrive();
    cl_wait();
}

}  // namespace

extern "C" void kernel_launch(void* const* d_in, const int* in_sizes, int n_in,
                              void* d_out, int out_size) {
    (void)in_sizes;
    (void)n_in;
    (void)out_size;
    const float* x = (const float*)d_in[0];
    const float* Wih1 = (const float*)d_in[1];
    const float* Whh1 = (const float*)d_in[2];
    const float* bih1 = (const float*)d_in[3];
    const float* bhh1 = (const float*)d_in[4];
    const float* Wih2 = (const float*)d_in[5];
    const float* Whh2 = (const float*)d_in[6];
    const float* bih2 = (const float*)d_in[7];
    const float* bhh2 = (const float*)d_in[8];
    const float* Wout = (const float*)d_in[9];
    const float* bout = (const float*)d_in[10];
    float* out = (float*)d_out;

    cudaFuncSetAttribute(lstm_mma_kernel,
                         cudaFuncAttributeMaxDynamicSharedMemorySize, SM_BYTES);

    cudaLaunchConfig_t cfg = {};
    cfg.gridDim = dim3((Bt / BC) * CL, 1, 1);  // 128 CTAs = 32 clusters of 4
    cfg.blockDim = dim3(NTH, 1, 1);
    cfg.dynamicSmemBytes = SM_BYTES;
    cfg.stream = 0;
    cudaLaunchAttribute attrs[1];
    attrs[0].id = cudaLaunchAttributeClusterDimension;
    attrs[0].val.clusterDim.x = CL;
    attrs[0].val.clusterDim.y = 1;
    attrs[0].val.clusterDim.z = 1;
    cfg.attrs = attrs;
    cfg.numAttrs = 1;

    cudaLaunchKernelEx(&cfg, lstm_mma_kernel, x, Wih1, Whh1, bih1, bhh1, Wih2,
                       Whh2, bih2, bhh2, Wout, bout, out);
}

// round 16
// speedup vs baseline: 1.8136x; 1.1155x over previous
#include <cuda_runtime.h>
#include <cuda_fp16.h>
#include <cstdint>

// LSTMPredictor: B=256, T=1024, H=128, 2-layer LSTM + linear head.
// 32 clusters x 4 CTAs x 256 threads. Layer-pipelined: iteration i computes
// h1(i) and h2(i-1); ONE cluster barrier per iteration. fp16 mma.sync
// m16n8k16 (fp32 accum), weights register-resident, h half2-packed [k/2][b].
// R14 merged body (all 24 MMAs up front, one __syncthreads, both epilogues
// back-to-back). R15: activations via MUFU.TANH (tanh.approx.f32):
// tanh = 1 MUFU, sigmoid = 0.5*tanh(x/2)+0.5 -> 10 MUFU/thread/iter less
// and a shorter serial c->h chain.

namespace {

constexpr int Bt = 256;
constexpr int Tt = 1024;
constexpr int Ht = 128;
constexpr int CL = 4;
constexpr int BC = 8;
constexpr int NTH = 256;

// smem (32-bit words)
constexpr int OFF_HT1 = 0;      // h1: 2 slot x 64 kp x 8 b half2 = 1024 words
constexpr int OFF_HT2 = 1024;   // h2
constexpr int OFF_GA  = 2048;   // gates1 staging [128 r][8 b] fp32
constexpr int OFF_GB  = 3072;   // gates2 staging
constexpr int OFF_BS1 = 4096;   // 128
constexpr int OFF_WX  = 4224;   // 128
constexpr int OFF_BS2 = 4352;   // 128
constexpr int OFF_WO  = 4480;   // 128
constexpr int OFF_X   = 4608;   // 2 slot x 8
constexpr int OFF_BO  = 4624;   // 1 (+pad)
constexpr int SM_FLOATS = 4628;
constexpr int SM_BYTES = SM_FLOATS * 4;  // ~18.5 KB

__device__ __forceinline__ uint32_t s2u(const void* p) {
    return (uint32_t)__cvta_generic_to_shared(p);
}
__device__ __forceinline__ uint32_t pkh2(float a, float b) {
    __half2 h = __halves2half2(__float2half_rn(a), __float2half_rn(b));
    return *reinterpret_cast<uint32_t*>(&h);
}
// m16n8k16 row.col f16 mma, fp32 accum
__device__ __forceinline__ void mma16(float* d, const uint32_t* a, uint32_t b0,
                                      uint32_t b1) {
    asm volatile(
        "mma.sync.aligned.m16n8k16.row.col.f32.f16.f16.f32 "
        "{%0,%1,%2,%3}, {%4,%5,%6,%7}, {%8,%9}, {%0,%1,%2,%3};"
        : "+f"(d[0]), "+f"(d[1]), "+f"(d[2]), "+f"(d[3])
        : "r"(a[0]), "r"(a[1]), "r"(a[2]), "r"(a[3]), "r"(b0), "r"(b1));
}
__device__ __forceinline__ void st_remote_h(uint32_t laddr, uint32_t peer,
                                            unsigned short v) {
    uint32_t r;
    asm("mapa.shared::cluster.u32 %0, %1, %2;" : "=r"(r) : "r"(laddr), "r"(peer));
    asm volatile("st.shared::cluster.u16 [%0], %1;" ::"r"(r), "h"(v) : "memory");
}
__device__ __forceinline__ void cl_arrive() {
    asm volatile("barrier.cluster.arrive.aligned;" ::: "memory");
}
__device__ __forceinline__ void cl_wait() {
    asm volatile("barrier.cluster.wait.aligned;" ::: "memory");
}
// MUFU.TANH-based activations (sm_75+ generic PTX)
__device__ __forceinline__ float tanh_mufu(float x) {
    float r;
    asm("tanh.approx.f32 %0, %1;" : "=f"(r) : "f"(x));
    return r;
}
__device__ __forceinline__ float sigf(float x) {
    return fmaf(tanh_mufu(0.5f * x), 0.5f, 0.5f);
}

__global__ void __launch_bounds__(NTH, 1) lstm_mma_kernel(
    const float* __restrict__ x, const float* __restrict__ Wih1,
    const float* __restrict__ Whh1, const float* __restrict__ bih1,
    const float* __restrict__ bhh1, const float* __restrict__ Wih2,
    const float* __restrict__ Whh2, const float* __restrict__ bih2,
    const float* __restrict__ bhh2, const float* __restrict__ Wout,
    const float* __restrict__ bout, float* __restrict__ out) {
    extern __shared__ float sm[];
    uint32_t* hH1 = reinterpret_cast<uint32_t*>(sm + OFF_HT1);
    uint32_t* hH2 = reinterpret_cast<uint32_t*>(sm + OFF_HT2);
    float* gbA = sm + OFF_GA;
    float* gbB = sm + OFF_GB;
    float* bs1s = sm + OFF_BS1;
    float* wxs = sm + OFF_WX;
    float* bs2s = sm + OFF_BS2;
    float* wos = sm + OFF_WO;
    float* xS = sm + OFF_X;
    float* boS = sm + OFF_BO;

    const int tid = threadIdx.x;
    const int lane = tid & 31;
    const int warp = tid >> 5;
    const int rank = blockIdx.x & 3;
    const int bbase = (blockIdx.x >> 2) * BC;
    const int U0 = rank * 32;

    // ---- MMA fragment coordinates (m16n8k16) ----
    const int q = lane & 3;
    const int g8 = lane >> 2;
    const int lr0 = warp * 16 + g8;
    const int lr1 = lr0 + 8;
    const int qg = q * 8 + g8;  // B-frag word offset within kt block
    const int G0 = ((lr0 >> 5) << 7) + U0 + (lr0 & 31);
    const int G1 = G0 + 8;

    // ---- weights -> registers as fp16 A-fragments (8 kt x 4 regs each) ----
    uint32_t w1[32], w2h[32], w2i[32];
#pragma unroll
    for (int kt = 0; kt < 8; ++kt) {
        const int k0 = kt * 16 + q * 2;
        w1[kt * 4 + 0] = pkh2(Whh1[G0 * Ht + k0], Whh1[G0 * Ht + k0 + 1]);
        w1[kt * 4 + 1] = pkh2(Whh1[G1 * Ht + k0], Whh1[G1 * Ht + k0 + 1]);
        w1[kt * 4 + 2] = pkh2(Whh1[G0 * Ht + k0 + 8], Whh1[G0 * Ht + k0 + 9]);
        w1[kt * 4 + 3] = pkh2(Whh1[G1 * Ht + k0 + 8], Whh1[G1 * Ht + k0 + 9]);
        w2h[kt * 4 + 0] = pkh2(Whh2[G0 * Ht + k0], Whh2[G0 * Ht + k0 + 1]);
        w2h[kt * 4 + 1] = pkh2(Whh2[G1 * Ht + k0], Whh2[G1 * Ht + k0 + 1]);
        w2h[kt * 4 + 2] = pkh2(Whh2[G0 * Ht + k0 + 8], Whh2[G0 * Ht + k0 + 9]);
        w2h[kt * 4 + 3] = pkh2(Whh2[G1 * Ht + k0 + 8], Whh2[G1 * Ht + k0 + 9]);
        w2i[kt * 4 + 0] = pkh2(Wih2[G0 * Ht + k0], Wih2[G0 * Ht + k0 + 1]);
        w2i[kt * 4 + 1] = pkh2(Wih2[G1 * Ht + k0], Wih2[G1 * Ht + k0 + 1]);
        w2i[kt * 4 + 2] = pkh2(Wih2[G0 * Ht + k0 + 8], Wih2[G0 * Ht + k0 + 9]);
        w2i[kt * 4 + 3] = pkh2(Wih2[G1 * Ht + k0 + 8], Wih2[G1 * Ht + k0 + 9]);
    }

    // ---- biases / small vectors into SMEM; zero h slots ----
    for (int r = tid; r < 128; r += NTH) {
        const int G = ((r >> 5) << 7) + U0 + (r & 31);
        bs1s[r] = bih1[G] + bhh1[G];
        wxs[r] = Wih1[G];
        bs2s[r] = bih2[G] + bhh2[G];
        wos[r] = Wout[r];
    }
    for (int i = tid; i < 2048; i += NTH) sm[OFF_HT1 + i] = 0.0f;  // h tiles
    if (tid == 0) boS[0] = bout[0];
    if (tid < BC) xS[tid] = x[(bbase + tid) * Tt + 0];  // x(0) -> slot 0
    __syncthreads();
    cl_arrive();
    cl_wait();  // peers' h buffers zeroed

    const uint32_t h1u = s2u(hH1);
    const uint32_t h2u = s2u(hH2);
    const uint32_t p1 = (rank + 1) & 3, p2r = (rank + 2) & 3, p3 = (rank + 3) & 3;
    const float boutr = boS[0];

    // epilogue mapping: bb = tid&7, unit gU = U0 + (tid>>3)
    const int bb = tid & 7;
    const int uu = tid >> 3;
    const int gU = U0 + uu;
    const uint32_t hbyte = (uint32_t)(((gU >> 1) * 8 + bb) * 4 + (gU & 1) * 2);
    const float bA0 = bs1s[0 * 32 + uu], bA1 = bs1s[1 * 32 + uu];
    const float bA2 = bs1s[2 * 32 + uu], bA3 = bs1s[3 * 32 + uu];
    const float wx0 = wxs[0 * 32 + uu], wx1 = wxs[1 * 32 + uu];
    const float wx2 = wxs[2 * 32 + uu], wx3 = wxs[3 * 32 + uu];
    const float bB0 = bs2s[0 * 32 + uu], bB1 = bs2s[1 * 32 + uu];
    const float bB2 = bs2s[2 * 32 + uu], bB3 = bs2s[3 * 32 + uu];
    // output-head weights (warps 6,7)
    const float wo0 = wos[2 * lane], wo1 = wos[2 * lane + 1];
    const float wo2 = wos[2 * lane + 64], wo3 = wos[2 * lane + 65];

    float c1 = 0.0f, c2 = 0.0f;

    // iteration i: h1(i) -> hH1 slot i&1 ; h2(i-1) -> hH2 slot (i-1)&1
    for (int i = 0; i <= Tt; ++i) {
        const int p = i & 1;
        const int pp = p ^ 1;
        const bool doA = (i < Tt);
        const bool doB = (i > 0);

        const uint32_t* h1p = hH1 + pp * 512;  // h1(i-1)
        const uint32_t* h2p = hH2 + p * 512;   // h2(i-2)

        // ===== all MMAs up front: D1 = W1@h1 ; D2 = W2h@h2 + W2i@h1 =====
        float d1a[4] = {0, 0, 0, 0}, d1b[4] = {0, 0, 0, 0};
        float d2a[4] = {0, 0, 0, 0}, d2b[4] = {0, 0, 0, 0};
        float d2c[4] = {0, 0, 0, 0}, d2d[4] = {0, 0, 0, 0};
        if (doA && doB) {
#pragma unroll
            for (int kt = 0; kt < 8; ++kt) {
                const uint32_t b0 = h1p[kt * 64 + qg];
                const uint32_t b1 = h1p[kt * 64 + 32 + qg];
                const uint32_t e0 = h2p[kt * 64 + qg];
                const uint32_t e1 = h2p[kt * 64 + 32 + qg];
                mma16((kt & 1) ? d1b : d1a, &w1[kt * 4], b0, b1);
                mma16((kt & 1) ? d2b : d2a, &w2h[kt * 4], e0, e1);
                mma16((kt & 1) ? d2d : d2c, &w2i[kt * 4], b0, b1);
            }
        } else if (doA) {  // i == 0
#pragma unroll
            for (int kt = 0; kt < 8; ++kt) {
                const uint32_t b0 = h1p[kt * 64 + qg];
                const uint32_t b1 = h1p[kt * 64 + 32 + qg];
                mma16((kt & 1) ? d1b : d1a, &w1[kt * 4], b0, b1);
            }
        } else {  // i == Tt
#pragma unroll
            for (int kt = 0; kt < 8; ++kt) {
                const uint32_t b0 = h1p[kt * 64 + qg];
                const uint32_t b1 = h1p[kt * 64 + 32 + qg];
                const uint32_t e0 = h2p[kt * 64 + qg];
                const uint32_t e1 = h2p[kt * 64 + 32 + qg];
                mma16((kt & 1) ? d2b : d2a, &w2h[kt * 4], e0, e1);
                mma16((kt & 1) ? d2d : d2c, &w2i[kt * 4], b0, b1);
            }
        }
        // stage both gate tiles, then ONE sync
        if (doA) {
            float2* gA2 = reinterpret_cast<float2*>(gbA);
            gA2[lr0 * 4 + q] = make_float2(d1a[0] + d1b[0], d1a[1] + d1b[1]);
            gA2[lr1 * 4 + q] = make_float2(d1a[2] + d1b[2], d1a[3] + d1b[3]);
        }
        if (doB) {
            float2* gB2 = reinterpret_cast<float2*>(gbB);
            gB2[lr0 * 4 + q] =
                make_float2(d2a[0] + d2b[0] + d2c[0] + d2d[0],
                            d2a[1] + d2b[1] + d2c[1] + d2d[1]);
            gB2[lr1 * 4 + q] =
                make_float2(d2a[2] + d2b[2] + d2c[2] + d2d[2],
                            d2a[3] + d2b[3] + d2c[3] + d2d[3]);
        }
        __syncthreads();

        // ===== both epilogues back-to-back (MUFU.TANH, short chains) =====
        if (doA) {
            const float xv = xS[p * 8 + bb];
            const float gi = gbA[(0 * 32 + uu) * 8 + bb] + bA0 + xv * wx0;
            const float gf = gbA[(1 * 32 + uu) * 8 + bb] + bA1 + xv * wx1;
            const float gg = gbA[(2 * 32 + uu) * 8 + bb] + bA2 + xv * wx2;
            const float go = gbA[(3 * 32 + uu) * 8 + bb] + bA3 + xv * wx3;
            c1 = sigf(gf) * c1 + sigf(gi) * tanh_mufu(gg);
            const float h1f = sigf(go) * tanh_mufu(c1);
            const __half h1h = __float2half_rn(h1f);
            const unsigned short h1b =
                *reinterpret_cast<const unsigned short*>(&h1h);
            const uint32_t la = h1u + (uint32_t)p * 2048u + hbyte;
            asm volatile("st.shared.u16 [%0], %1;" ::"r"(la), "h"(h1b)
                         : "memory");
            st_remote_h(la, p1, h1b);
            st_remote_h(la, p2r, h1b);
            st_remote_h(la, p3, h1b);
        }
        if (doB) {
            const float gi = gbB[(0 * 32 + uu) * 8 + bb] + bB0;
            const float gf = gbB[(1 * 32 + uu) * 8 + bb] + bB1;
            const float gg = gbB[(2 * 32 + uu) * 8 + bb] + bB2;
            const float go = gbB[(3 * 32 + uu) * 8 + bb] + bB3;
            c2 = sigf(gf) * c2 + sigf(gi) * tanh_mufu(gg);
            const float h2f = sigf(go) * tanh_mufu(c2);
            const __half h2h = __float2half_rn(h2f);
            const unsigned short h2b =
                *reinterpret_cast<const unsigned short*>(&h2h);
            const uint32_t la = h2u + (uint32_t)pp * 2048u + hbyte;
            asm volatile("st.shared.u16 [%0], %1;" ::"r"(la), "h"(h2b)
                         : "memory");
            st_remote_h(la, p1, h2b);
            st_remote_h(la, p2r, h2b);
            st_remote_h(la, p3, h2b);
        }

        // ===== single cluster barrier: h1(i) + h2(i-1) published =====
        cl_arrive();
        if (tid < BC && doA) {  // x prefetch in the arrive->wait gap
            xS[pp * 8 + tid] =
                (i + 1 < Tt) ? x[(bbase + tid) * Tt + (i + 1)] : 0.0f;
        }
        cl_wait();

        // ===== output(i-1): warps 6,7 (overlaps next iteration's MMA) =====
        if (doB && warp >= 6) {
            const int bl = rank * 2 + (warp - 6);
            const uint32_t* h2c = hH2 + pp * 512;
            const __half2 ha =
                *reinterpret_cast<const __half2*>(&h2c[lane * 8 + bl]);
            const __half2 hb =
                *reinterpret_cast<const __half2*>(&h2c[(lane + 32) * 8 + bl]);
            const float2 fa = __half22float2(ha);
            const float2 fb = __half22float2(hb);
            float s = fa.x * wo0 + fa.y * wo1 + fb.x * wo2 + fb.y * wo3;
            s += __shfl_xor_sync(0xffffffffu, s, 16);
            s += __shfl_xor_sync(0xffffffffu, s, 8);
            s += __shfl_xor_sync(0xffffffffu, s, 4);
            s += __shfl_xor_sync(0xffffffffu, s, 2);
            s += __shfl_xor_sync(0xffffffffu, s, 1);
            if (lane == 0) out[(bbase + bl) * Tt + (i - 1)] = s + boutr;
        }
    }

    // exit safety
    cl_arrive();
    cl_wait();
}

}  // namespace

extern "C" void kernel_launch(void* const* d_in, const int* in_sizes, int n_in,
                              void* d_out, int out_size) {
    (void)in_sizes;
    (void)n_in;
    (void)out_size;
    const float* x = (const float*)d_in[0];
    const float* Wih1 = (const float*)d_in[1];
    const float* Whh1 = (const float*)d_in[2];
    const float* bih1 = (const float*)d_in[3];
    const float* bhh1 = (const float*)d_in[4];
    const float* Wih2 = (const float*)d_in[5];
    const float* Whh2 = (const float*)d_in[6];
    const float* bih2 = (const float*)d_in[7];
    const float* bhh2 = (const float*)d_in[8];
    const float* Wout = (const float*)d_in[9];
    const float* bout = (const float*)d_in[10];
    float* out = (float*)d_out;

    cudaFuncSetAttribute(lstm_mma_kernel,
                         cudaFuncAttributeMaxDynamicSharedMemorySize, SM_BYTES);

    cudaLaunchConfig_t cfg = {};
    cfg.gridDim = dim3((Bt / BC) * CL, 1, 1);  // 128 CTAs = 32 clusters of 4
    cfg.blockDim = dim3(NTH, 1, 1);
    cfg.dynamicSmemBytes = SM_BYTES;
    cfg.stream = 0;
    cudaLaunchAttribute attrs[1];
    attrs[0].id = cudaLaunchAttributeClusterDimension;
    attrs[0].val.clusterDim.x = CL;
    attrs[0].val.clusterDim.y = 1;
    attrs[0].val.clusterDim.z = 1;
    cfg.attrs = attrs;
    cfg.numAttrs = 1;

    cudaLaunchKernelEx(&cfg, lstm_mma_kernel, x, Wih1, Whh1, bih1, bhh1, Wih2,
                       Whh2, bih2, bhh2, Wout, bout, out);
}